// round 14
// baseline (speedup 1.0000x reference)
#include <cuda_runtime.h>
#include <math.h>

// Problem constants
#define NB    256
#define TT    2048
#define CIN   18      // C*S = 9*2
#define H1C   32
#define H2C   64
#define ND    3
#define ED    64
#define TILE  256     // t-positions per tile; 2 per thread
#define NCODE 240
#define NTILES (NB * (TT / TILE))   // 2048
#define GRID  444                   // 148 SM x 3 resident blocks (persistent)
#define XW    264                   // staged x row: t0-4 .. t0+259
#define H1W   260                   // h1 row: col j = position t0+j-1, j=0..257

// Output packing (flattened, concatenated, float32):
// codes [B,T], out [B,64,T], perplexity [1], probs [240]
#define OFF_CODES 0L
#define OFF_OUT   ((long)NB * TT)                        // 524288
#define OFF_PERP  (OFF_OUT + (long)NB * ED * TT)         // 34078720
#define OFF_PROBS (OFF_PERP + 1)                         // 34078721

__device__ int g_counts[NCODE];

// Replicate jnp.linspace(-1, 1, L, float32)
__device__ __forceinline__ float lspf(int i, int L) {
    float step = 2.0f / (float)(L - 1);
    return -1.0f + (float)i * step;
}

// argmin vs linspace(-1,1,L) == count of midpoints strictly below x
template <int L>
__device__ __forceinline__ int quant_idx(float feat) {
    int idx = 0;
    #pragma unroll
    for (int i = 0; i < L - 1; i++) {
        float m = 0.5f * (lspf(i, L) + lspf(i + 1, L));
        idx += (feat > m);
    }
    return idx;
}

struct Smem {
    float w1s[CIN * 3 * H1C];   // [cin*3+k][co]
    float w2s[H1C * 3 * H2C];   // [ci*3+k][co]
    float w3s[ND * H2C];        // [d][co]
    float wps[ED * ND];         // [e][d]
    float b1s[H1C];
    float b2s[H2C];
    float b3s[4];
    float bps[ED];
    // union region: per tile, first holds staged x [CIN][XW] (4752 floats),
    // then is overwritten by h1 [H1C][H1W] (8320 floats).
    float uni[H1C * H1W];
    int   hist[NCODE];
};

__global__ __launch_bounds__(128, 3) void fsq_main_kernel(
    const float* __restrict__ x,
    const float* __restrict__ w1, const float* __restrict__ b1,
    const float* __restrict__ w2, const float* __restrict__ b2,
    const float* __restrict__ w3, const float* __restrict__ b3,
    const float* __restrict__ wp, const float* __restrict__ bp,
    float* __restrict__ out)
{
    extern __shared__ Smem smem[];
    Smem* S = smem;
    const int tid = threadIdx.x;

    // ---- stage weights once per persistent block ----
    for (int i = tid; i < CIN * 3 * H1C; i += 128) {
        int co = i % H1C, rk = i / H1C;
        S->w1s[i] = w1[co * (CIN * 3) + rk];
    }
    for (int i = tid; i < H1C * 3 * H2C; i += 128) {
        int co = i % H2C, rk = i / H2C;
        S->w2s[i] = w2[co * (H1C * 3) + rk];
    }
    for (int i = tid; i < ND * H2C; i += 128) S->w3s[i] = w3[i];
    for (int i = tid; i < ED * ND;  i += 128) S->wps[i] = wp[i];
    if (tid < H1C) S->b1s[tid] = b1[tid];
    if (tid < H2C) S->b2s[tid] = b2[tid];
    if (tid < ND)  S->b3s[tid] = b3[tid];
    if (tid < ED)  S->bps[tid] = bp[tid];
    for (int i = tid; i < NCODE; i += 128) S->hist[i] = 0;
    __syncthreads();

    // ---- persistent grid-stride over tiles ----
    for (int tile = blockIdx.x; tile < NTILES; tile += GRID) {
        const int b  = tile >> 3;            // TT/TILE = 8 tiles per batch row
        const int t0 = (tile & 7) * TILE;
        const float* xb = x + (long)b * CIN * TT;

        // ---- stage x tile [CIN][XW] covering positions t0-4 .. t0+259 ----
        for (int idx = tid; idx < CIN * (XW / 4); idx += 128) {
            int cin = idx / (XW / 4), q = idx % (XW / 4);
            int p0 = t0 - 4 + q * 4;
            const float* gx = xb + cin * TT;
            float4 v;
            if (p0 >= 0 && p0 + 3 < TT) {
                v = __ldg((const float4*)(gx + p0));
            } else {
                v.x = (p0 >= 0     && p0 < TT)     ? __ldg(gx + p0)     : 0.0f;
                v.y = (p0 + 1 >= 0 && p0 + 1 < TT) ? __ldg(gx + p0 + 1) : 0.0f;
                v.z = (p0 + 2 >= 0 && p0 + 2 < TT) ? __ldg(gx + p0 + 2) : 0.0f;
                v.w = (p0 + 3 >= 0 && p0 + 3 < TT) ? __ldg(gx + p0 + 3) : 0.0f;
            }
            *(float4*)&S->uni[cin * XW + q * 4] = v;
        }
        __syncthreads();

        // ---- conv1 (18->32, k3, pad1): two columns per thread from SMEM x.
        // acc from 0, strict (cin, kw) chain per channel, bias in epilogue.
        float h1A[H1C], h1B[H1C];
        {
            const int jA = tid, jB = tid + 128;
            float accA[H1C], accB[H1C];
            #pragma unroll
            for (int c = 0; c < H1C; c++) { accA[c] = 0.0f; accB[c] = 0.0f; }
            #pragma unroll 1
            for (int cin = 0; cin < CIN; cin++) {
                const float* xr = &S->uni[cin * XW];
                float a0A = xr[jA + 2], a1A = xr[jA + 3], a2A = xr[jA + 4];
                float a0B = xr[jB + 2], a1B = xr[jB + 3], a2B = xr[jB + 4];
                const float4* u0 = (const float4*)&S->w1s[cin * 96];
                const float4* u1 = (const float4*)&S->w1s[cin * 96 + 32];
                const float4* u2 = (const float4*)&S->w1s[cin * 96 + 64];
                #pragma unroll
                for (int j = 0; j < 8; j++) {
                    float4 v0 = u0[j], v1 = u1[j], v2 = u2[j];
                    #pragma unroll
                    for (int q = 0; q < 4; q++) {
                        float w0 = (&v0.x)[q], w1v = (&v1.x)[q], w2v = (&v2.x)[q];
                        int c = 4 * j + q;
                        accA[c] = fmaf(a0A, w0, accA[c]);
                        accA[c] = fmaf(a1A, w1v, accA[c]);
                        accA[c] = fmaf(a2A, w2v, accA[c]);
                        accB[c] = fmaf(a0B, w0, accB[c]);
                        accB[c] = fmaf(a1B, w1v, accB[c]);
                        accB[c] = fmaf(a2B, w2v, accB[c]);
                    }
                }
            }
            const bool vA = (t0 + tid) > 0;        // position t0+jA-1 >= 0
            #pragma unroll
            for (int c = 0; c < H1C; c++) {
                h1A[c] = vA ? fmaxf(__fadd_rn(accA[c], S->b1s[c]), 0.0f) : 0.0f;
                h1B[c] = fmaxf(__fadd_rn(accB[c], S->b1s[c]), 0.0f);
            }
        }
        // leftover cols 256,257: 64 independent (col, channel) chains
        float leftv = 0.0f;
        if (tid < 64) {
            const int col = 256 + (tid >> 5);
            const int ch  = tid & 31;
            float a = 0.0f;
            #pragma unroll 1
            for (int cin = 0; cin < CIN; cin++) {
                const float* xr = &S->uni[cin * XW];
                a = fmaf(xr[col + 2], S->w1s[(cin * 3 + 0) * H1C + ch], a);
                a = fmaf(xr[col + 3], S->w1s[(cin * 3 + 1) * H1C + ch], a);
                a = fmaf(xr[col + 4], S->w1s[(cin * 3 + 2) * H1C + ch], a);
            }
            const bool vc = (t0 + col - 1) < TT;
            leftv = vc ? fmaxf(__fadd_rn(a, S->b1s[ch]), 0.0f) : 0.0f;
        }
        __syncthreads();   // all x reads done; safe to overwrite uni with h1

        // ---- write h1 into uni (overwriting staged x) ----
        {
            #pragma unroll
            for (int c = 0; c < H1C; c++) {
                S->uni[c * H1W + tid]       = h1A[c];
                S->uni[c * H1W + tid + 128] = h1B[c];
            }
            if (tid < 64) {
                const int col = 256 + (tid >> 5);
                const int ch  = tid & 31;
                S->uni[ch * H1W + col] = leftv;
            }
        }
        __syncthreads();

        // ---- conv2 (32->64, k3, pad1) + fused conv3 partials, in two
        // 32-channel halves to halve live accumulator registers.
        // Per-channel (ci, kw) FMA chain and conv3's ascending-channel
        // chain are both preserved exactly (half 0 = ch0-31, half 1 = ch32-63).
        const int tA = t0 + 2 * tid;
        float s00 = 0.0f, s01 = 0.0f, s02 = 0.0f;
        float s10 = 0.0f, s11 = 0.0f, s12 = 0.0f;
        #pragma unroll 1
        for (int half = 0; half < 2; half++) {
            const int cbase = half * 32;
            float acc0[32], acc1[32];
            #pragma unroll
            for (int j = 0; j < 32; j++) { acc0[j] = 0.0f; acc1[j] = 0.0f; }
            #pragma unroll 1
            for (int ci = 0; ci < H1C; ci++) {
                float2 hA = *(const float2*)&S->uni[ci * H1W + 2 * tid];
                float2 hB = *(const float2*)&S->uni[ci * H1W + 2 * tid + 2];
                float p0a0 = hA.x, p0a1 = hA.y, p0a2 = hB.x;
                float p1a0 = hA.y, p1a1 = hB.x, p1a2 = hB.y;
                const float4* u0 = (const float4*)&S->w2s[ci * 192 + cbase];
                const float4* u1 = (const float4*)&S->w2s[ci * 192 + 64 + cbase];
                const float4* u2 = (const float4*)&S->w2s[ci * 192 + 128 + cbase];
                #pragma unroll
                for (int j = 0; j < 8; j++) {
                    float4 v0 = u0[j], v1 = u1[j], v2 = u2[j];
                    #pragma unroll
                    for (int q = 0; q < 4; q++) {
                        float w0 = (&v0.x)[q], w1v = (&v1.x)[q], w2v = (&v2.x)[q];
                        int c = 4 * j + q;
                        acc0[c] = fmaf(p0a0, w0, acc0[c]);
                        acc0[c] = fmaf(p0a1, w1v, acc0[c]);
                        acc0[c] = fmaf(p0a2, w2v, acc0[c]);
                        acc1[c] = fmaf(p1a0, w0, acc1[c]);
                        acc1[c] = fmaf(p1a1, w1v, acc1[c]);
                        acc1[c] = fmaf(p1a2, w2v, acc1[c]);
                    }
                }
            }
            // bias + ReLU + conv3 partial sums for this half's channels,
            // consumed in ascending channel order (chain-exact).
            #pragma unroll
            for (int j = 0; j < 32; j++) {
                int c = cbase + j;
                float p0 = fmaxf(__fadd_rn(acc0[j], S->b2s[c]), 0.0f);
                float p1 = fmaxf(__fadd_rn(acc1[j], S->b2s[c]), 0.0f);
                s00 = fmaf(p0, S->w3s[c], s00);
                s01 = fmaf(p0, S->w3s[H2C + c], s01);
                s02 = fmaf(p0, S->w3s[2 * H2C + c], s02);
                s10 = fmaf(p1, S->w3s[c], s10);
                s11 = fmaf(p1, S->w3s[H2C + c], s11);
                s12 = fmaf(p1, S->w3s[2 * H2C + c], s12);
            }
        }

        // ---- tanh + FSQ + STE + projection ----
        float code_pair[2];
        float qv[2][3];
        #pragma unroll
        for (int p = 0; p < 2; p++) {
            float f0 = tanhf(__fadd_rn(p == 0 ? s00 : s10, S->b3s[0]));
            float f1 = tanhf(__fadd_rn(p == 0 ? s01 : s11, S->b3s[1]));
            float f2 = tanhf(__fadd_rn(p == 0 ? s02 : s12, S->b3s[2]));
            int i0 = quant_idx<8>(f0);
            int i1 = quant_idx<6>(f1);
            int i2 = quant_idx<5>(f2);
            qv[p][0] = __fadd_rn(f0, __fsub_rn(lspf(i0, 8), f0));
            qv[p][1] = __fadd_rn(f1, __fsub_rn(lspf(i1, 6), f1));
            qv[p][2] = __fadd_rn(f2, __fsub_rn(lspf(i2, 5), f2));
            int code = i0 + i1 * 8 + i2 * 48;
            atomicAdd(&S->hist[code], 1);
            code_pair[p] = (float)code;
        }
        *(float2*)&out[OFF_CODES + (long)b * TT + tA] =
            make_float2(code_pair[0], code_pair[1]);

        {
            long ob = OFF_OUT + (long)b * ED * TT + tA;
            #pragma unroll
            for (int e = 0; e < ED; e++) {
                float w0 = S->wps[e*3+0], w1v = S->wps[e*3+1], w2v = S->wps[e*3+2];
                float be = S->bps[e];
                float r0 = __fmul_rn(qv[0][0], w0);
                r0 = fmaf(qv[0][1], w1v, r0);
                r0 = fmaf(qv[0][2], w2v, r0);
                float r1 = __fmul_rn(qv[1][0], w0);
                r1 = fmaf(qv[1][1], w1v, r1);
                r1 = fmaf(qv[1][2], w2v, r1);
                *(float2*)&out[ob + (long)e * TT] =
                    make_float2(__fadd_rn(r0, be), __fadd_rn(r1, be));
            }
        }
        __syncthreads();   // h1 reads done before next tile's x staging
    }

    // ---- flush per-block histogram once ----
    for (int i = tid; i < NCODE; i += 128) {
        int h = S->hist[i];
        if (h) atomicAdd(&g_counts[i], h);
    }
}

__global__ void finalize_kernel(float* __restrict__ out) {
    __shared__ float red[256];
    int tid = threadIdx.x;
    float term = 0.0f;
    if (tid < NCODE) {
        float c = (float)g_counts[tid];
        g_counts[tid] = 0;                       // reset for next graph replay
        float p = c * (1.0f / (float)((long)NB * TT));
        out[OFF_PROBS + tid] = p;
        if (p > 0.0f) term = -p * logf(p);
    }
    red[tid] = term;
    __syncthreads();
    #pragma unroll
    for (int s = 128; s > 0; s >>= 1) {
        if (tid < s) red[tid] += red[tid + s];
        __syncthreads();
    }
    if (tid == 0) out[OFF_PERP] = fmaxf(expf(red[0]), 1.0f);
}

extern "C" void kernel_launch(void* const* d_in, const int* in_sizes, int n_in,
                              void* d_out, int out_size) {
    const float* x  = (const float*)d_in[0];
    const float* w1 = (const float*)d_in[1];
    const float* b1 = (const float*)d_in[2];
    const float* w2 = (const float*)d_in[3];
    const float* b2 = (const float*)d_in[4];
    const float* w3 = (const float*)d_in[5];
    const float* b3 = (const float*)d_in[6];
    const float* wp = (const float*)d_in[7];
    const float* bp = (const float*)d_in[8];
    float* out = (float*)d_out;

    cudaFuncSetAttribute(fsq_main_kernel,
                         cudaFuncAttributeMaxDynamicSharedMemorySize,
                         (int)sizeof(Smem));

    fsq_main_kernel<<<GRID, 128, sizeof(Smem)>>>(
        x, w1, b1, w2, b2, w3, b3, wp, bp, out);
    finalize_kernel<<<1, 256>>>(out);
}

// round 15
// speedup vs baseline: 1.0544x; 1.0544x over previous
#include <cuda_runtime.h>
#include <math.h>

// Problem constants
#define NB    256
#define TT    2048
#define CIN   18      // C*S = 9*2
#define H1C   32
#define H2C   64
#define ND    3
#define ED    64
#define TILE  256     // t-positions per tile; 2 per thread
#define NCODE 240
#define NTILES (NB * (TT / TILE))   // 2048
#define GRID  444                   // 148 SM x 3 resident blocks (persistent)
#define XW    264                   // staged x row: t0-4 .. t0+259
#define H1W   260                   // h1 row: col j = position t0+j-1, j=0..257

// Output packing (flattened, concatenated, float32):
// codes [B,T], out [B,64,T], perplexity [1], probs [240]
#define OFF_CODES 0L
#define OFF_OUT   ((long)NB * TT)                        // 524288
#define OFF_PERP  (OFF_OUT + (long)NB * ED * TT)         // 34078720
#define OFF_PROBS (OFF_PERP + 1)                         // 34078721

__device__ int g_counts[NCODE];
__device__ int g_done;

// Replicate jnp.linspace(-1, 1, L, float32)
__device__ __forceinline__ float lspf(int i, int L) {
    float step = 2.0f / (float)(L - 1);
    return -1.0f + (float)i * step;
}

// argmin vs linspace(-1,1,L) == count of midpoints strictly below x
template <int L>
__device__ __forceinline__ int quant_idx(float feat) {
    int idx = 0;
    #pragma unroll
    for (int i = 0; i < L - 1; i++) {
        float m = 0.5f * (lspf(i, L) + lspf(i + 1, L));
        idx += (feat > m);
    }
    return idx;
}

struct Smem {
    float w1s[CIN * 3 * H1C];   // [cin*3+k][co]
    float w2s[H1C * 3 * H2C];   // [ci*3+k][co]
    float w3s[ND * H2C];        // [d][co]
    float wps[ED * ND];         // [e][d]
    float b1s[H1C];
    float b2s[H2C];
    float b3s[4];
    float bps[ED];
    // union region: per tile, first holds staged x [CIN][XW] (4752 floats),
    // then is overwritten by h1 [H1C][H1W] (8320 floats).
    float uni[H1C * H1W];
    int   hist[NCODE];
};

__global__ __launch_bounds__(128, 3) void fsq_main_kernel(
    const float* __restrict__ x,
    const float* __restrict__ w1, const float* __restrict__ b1,
    const float* __restrict__ w2, const float* __restrict__ b2,
    const float* __restrict__ w3, const float* __restrict__ b3,
    const float* __restrict__ wp, const float* __restrict__ bp,
    float* __restrict__ out)
{
    extern __shared__ Smem smem[];
    Smem* S = smem;
    const int tid = threadIdx.x;

    // ---- stage weights once per persistent block ----
    for (int i = tid; i < CIN * 3 * H1C; i += 128) {
        int co = i % H1C, rk = i / H1C;
        S->w1s[i] = w1[co * (CIN * 3) + rk];
    }
    for (int i = tid; i < H1C * 3 * H2C; i += 128) {
        int co = i % H2C, rk = i / H2C;
        S->w2s[i] = w2[co * (H1C * 3) + rk];
    }
    for (int i = tid; i < ND * H2C; i += 128) S->w3s[i] = w3[i];
    for (int i = tid; i < ED * ND;  i += 128) S->wps[i] = wp[i];
    if (tid < H1C) S->b1s[tid] = b1[tid];
    if (tid < H2C) S->b2s[tid] = b2[tid];
    if (tid < ND)  S->b3s[tid] = b3[tid];
    if (tid < ED)  S->bps[tid] = bp[tid];
    for (int i = tid; i < NCODE; i += 128) S->hist[i] = 0;
    __syncthreads();

    // ---- persistent grid-stride over tiles ----
    for (int tile = blockIdx.x; tile < NTILES; tile += GRID) {
        const int b  = tile >> 3;            // TT/TILE = 8 tiles per batch row
        const int t0 = (tile & 7) * TILE;
        const float* xb = x + (long)b * CIN * TT;

        // ---- stage x tile [CIN][XW] covering positions t0-4 .. t0+259 ----
        for (int idx = tid; idx < CIN * (XW / 4); idx += 128) {
            int cin = idx / (XW / 4), q = idx % (XW / 4);
            int p0 = t0 - 4 + q * 4;
            const float* gx = xb + cin * TT;
            float4 v;
            if (p0 >= 0 && p0 + 3 < TT) {
                v = __ldg((const float4*)(gx + p0));
            } else {
                v.x = (p0 >= 0     && p0 < TT)     ? __ldg(gx + p0)     : 0.0f;
                v.y = (p0 + 1 >= 0 && p0 + 1 < TT) ? __ldg(gx + p0 + 1) : 0.0f;
                v.z = (p0 + 2 >= 0 && p0 + 2 < TT) ? __ldg(gx + p0 + 2) : 0.0f;
                v.w = (p0 + 3 >= 0 && p0 + 3 < TT) ? __ldg(gx + p0 + 3) : 0.0f;
            }
            *(float4*)&S->uni[cin * XW + q * 4] = v;
        }
        __syncthreads();

        // ---- conv1 (18->32, k3, pad1): two columns per thread from SMEM x.
        // acc from 0, strict (cin, kw) chain per channel, bias in epilogue.
        float h1A[H1C], h1B[H1C];
        {
            const int jA = tid, jB = tid + 128;
            float accA[H1C], accB[H1C];
            #pragma unroll
            for (int c = 0; c < H1C; c++) { accA[c] = 0.0f; accB[c] = 0.0f; }
            #pragma unroll 1
            for (int cin = 0; cin < CIN; cin++) {
                const float* xr = &S->uni[cin * XW];
                float a0A = xr[jA + 2], a1A = xr[jA + 3], a2A = xr[jA + 4];
                float a0B = xr[jB + 2], a1B = xr[jB + 3], a2B = xr[jB + 4];
                const float4* u0 = (const float4*)&S->w1s[cin * 96];
                const float4* u1 = (const float4*)&S->w1s[cin * 96 + 32];
                const float4* u2 = (const float4*)&S->w1s[cin * 96 + 64];
                #pragma unroll
                for (int j = 0; j < 8; j++) {
                    float4 v0 = u0[j], v1 = u1[j], v2 = u2[j];
                    #pragma unroll
                    for (int q = 0; q < 4; q++) {
                        float w0 = (&v0.x)[q], w1v = (&v1.x)[q], w2v = (&v2.x)[q];
                        int c = 4 * j + q;
                        accA[c] = fmaf(a0A, w0, accA[c]);
                        accA[c] = fmaf(a1A, w1v, accA[c]);
                        accA[c] = fmaf(a2A, w2v, accA[c]);
                        accB[c] = fmaf(a0B, w0, accB[c]);
                        accB[c] = fmaf(a1B, w1v, accB[c]);
                        accB[c] = fmaf(a2B, w2v, accB[c]);
                    }
                }
            }
            const bool vA = (t0 + tid) > 0;        // position t0+jA-1 >= 0
            #pragma unroll
            for (int c = 0; c < H1C; c++) {
                h1A[c] = vA ? fmaxf(__fadd_rn(accA[c], S->b1s[c]), 0.0f) : 0.0f;
                h1B[c] = fmaxf(__fadd_rn(accB[c], S->b1s[c]), 0.0f);
            }
        }
        // leftover cols 256,257: 64 independent (col, channel) chains
        float leftv = 0.0f;
        if (tid < 64) {
            const int col = 256 + (tid >> 5);
            const int ch  = tid & 31;
            float a = 0.0f;
            #pragma unroll 1
            for (int cin = 0; cin < CIN; cin++) {
                const float* xr = &S->uni[cin * XW];
                a = fmaf(xr[col + 2], S->w1s[(cin * 3 + 0) * H1C + ch], a);
                a = fmaf(xr[col + 3], S->w1s[(cin * 3 + 1) * H1C + ch], a);
                a = fmaf(xr[col + 4], S->w1s[(cin * 3 + 2) * H1C + ch], a);
            }
            const bool vc = (t0 + col - 1) < TT;
            leftv = vc ? fmaxf(__fadd_rn(a, S->b1s[ch]), 0.0f) : 0.0f;
        }
        __syncthreads();   // all x reads done; safe to overwrite uni with h1

        // ---- write h1 into uni (overwriting staged x) ----
        {
            #pragma unroll
            for (int c = 0; c < H1C; c++) {
                S->uni[c * H1W + tid]       = h1A[c];
                S->uni[c * H1W + tid + 128] = h1B[c];
            }
            if (tid < 64) {
                const int col = 256 + (tid >> 5);
                const int ch  = tid & 31;
                S->uni[ch * H1W + col] = leftv;
            }
        }
        __syncthreads();

        // ---- conv2 (32->64, k3, pad1): two adjacent positions per thread,
        // shared weight loads; strict (ci, kw) chain per channel (R13-exact).
        const int tA = t0 + 2 * tid;
        float acc0[H2C], acc1[H2C];
        #pragma unroll
        for (int c = 0; c < H2C; c++) { acc0[c] = 0.0f; acc1[c] = 0.0f; }
        #pragma unroll 1
        for (int ci = 0; ci < H1C; ci++) {
            float2 hA = *(const float2*)&S->uni[ci * H1W + 2 * tid];
            float2 hB = *(const float2*)&S->uni[ci * H1W + 2 * tid + 2];
            float p0a0 = hA.x, p0a1 = hA.y, p0a2 = hB.x;
            float p1a0 = hA.y, p1a1 = hB.x, p1a2 = hB.y;
            const float4* u0 = (const float4*)&S->w2s[ci * 192];
            const float4* u1 = (const float4*)&S->w2s[ci * 192 + 64];
            const float4* u2 = (const float4*)&S->w2s[ci * 192 + 128];
            #pragma unroll
            for (int j = 0; j < 16; j++) {
                float4 v0 = u0[j], v1 = u1[j], v2 = u2[j];
                #pragma unroll
                for (int q = 0; q < 4; q++) {
                    float w0 = (&v0.x)[q], w1v = (&v1.x)[q], w2v = (&v2.x)[q];
                    int c = 4 * j + q;
                    acc0[c] = fmaf(p0a0, w0, acc0[c]);
                    acc0[c] = fmaf(p0a1, w1v, acc0[c]);
                    acc0[c] = fmaf(p0a2, w2v, acc0[c]);
                    acc1[c] = fmaf(p1a0, w0, acc1[c]);
                    acc1[c] = fmaf(p1a1, w1v, acc1[c]);
                    acc1[c] = fmaf(p1a2, w2v, acc1[c]);
                }
            }
        }
        #pragma unroll
        for (int c = 0; c < H2C; c++) {
            acc0[c] = fmaxf(__fadd_rn(acc0[c], S->b2s[c]), 0.0f);
            acc1[c] = fmaxf(__fadd_rn(acc1[c], S->b2s[c]), 0.0f);
        }

        // ---- conv3 + tanh + FSQ + STE + projection (R13-exact) ----
        float code_pair[2];
        float qv[2][3];
        #pragma unroll
        for (int p = 0; p < 2; p++) {
            const float* ac = (p == 0) ? acc0 : acc1;
            float s0 = 0.0f, s1 = 0.0f, s2 = 0.0f;
            #pragma unroll
            for (int c = 0; c < H2C; c++) {
                s0 = fmaf(ac[c], S->w3s[0 * H2C + c], s0);
                s1 = fmaf(ac[c], S->w3s[1 * H2C + c], s1);
                s2 = fmaf(ac[c], S->w3s[2 * H2C + c], s2);
            }
            float f0 = tanhf(__fadd_rn(s0, S->b3s[0]));
            float f1 = tanhf(__fadd_rn(s1, S->b3s[1]));
            float f2 = tanhf(__fadd_rn(s2, S->b3s[2]));
            int i0 = quant_idx<8>(f0);
            int i1 = quant_idx<6>(f1);
            int i2 = quant_idx<5>(f2);
            qv[p][0] = __fadd_rn(f0, __fsub_rn(lspf(i0, 8), f0));
            qv[p][1] = __fadd_rn(f1, __fsub_rn(lspf(i1, 6), f1));
            qv[p][2] = __fadd_rn(f2, __fsub_rn(lspf(i2, 5), f2));
            int code = i0 + i1 * 8 + i2 * 48;
            atomicAdd(&S->hist[code], 1);
            code_pair[p] = (float)code;
        }
        *(float2*)&out[OFF_CODES + (long)b * TT + tA] =
            make_float2(code_pair[0], code_pair[1]);

        {
            long ob = OFF_OUT + (long)b * ED * TT + tA;
            #pragma unroll
            for (int e = 0; e < ED; e++) {
                float w0 = S->wps[e*3+0], w1v = S->wps[e*3+1], w2v = S->wps[e*3+2];
                float be = S->bps[e];
                float r0 = __fmul_rn(qv[0][0], w0);
                r0 = fmaf(qv[0][1], w1v, r0);
                r0 = fmaf(qv[0][2], w2v, r0);
                float r1 = __fmul_rn(qv[1][0], w0);
                r1 = fmaf(qv[1][1], w1v, r1);
                r1 = fmaf(qv[1][2], w2v, r1);
                *(float2*)&out[ob + (long)e * TT] =
                    make_float2(__fadd_rn(r0, be), __fadd_rn(r1, be));
            }
        }
        __syncthreads();   // h1 reads done before next tile's x staging
    }

    // ---- flush per-block histogram to global ----
    for (int i = tid; i < NCODE; i += 128) {
        int h = S->hist[i];
        if (h) atomicAdd(&g_counts[i], h);
    }

    // ---- last-block finalize (threadfence reduction pattern) ----
    __threadfence();
    __shared__ int is_last;
    __shared__ float red[128];
    if (tid == 0) {
        int d = atomicAdd(&g_done, 1);
        is_last = (d == GRID - 1);
    }
    __syncthreads();
    if (is_last) {
        float term = 0.0f;
        for (int i = tid; i < NCODE; i += 128) {       // i, then i+128: fixed order
            float c = (float)g_counts[i];
            g_counts[i] = 0;                            // reset for next replay
            float p = c * (1.0f / (float)((long)NB * TT));
            out[OFF_PROBS + i] = p;
            if (p > 0.0f) term += -p * logf(p);
        }
        red[tid] = term;
        __syncthreads();
        #pragma unroll
        for (int s = 64; s > 0; s >>= 1) {
            if (tid < s) red[tid] += red[tid + s];
            __syncthreads();
        }
        if (tid == 0) {
            out[OFF_PERP] = fmaxf(expf(red[0]), 1.0f);
            g_done = 0;                                 // reset for next replay
        }
    }
}

extern "C" void kernel_launch(void* const* d_in, const int* in_sizes, int n_in,
                              void* d_out, int out_size) {
    const float* x  = (const float*)d_in[0];
    const float* w1 = (const float*)d_in[1];
    const float* b1 = (const float*)d_in[2];
    const float* w2 = (const float*)d_in[3];
    const float* b2 = (const float*)d_in[4];
    const float* w3 = (const float*)d_in[5];
    const float* b3 = (const float*)d_in[6];
    const float* wp = (const float*)d_in[7];
    const float* bp = (const float*)d_in[8];
    float* out = (float*)d_out;

    cudaFuncSetAttribute(fsq_main_kernel,
                         cudaFuncAttributeMaxDynamicSharedMemorySize,
                         (int)sizeof(Smem));

    fsq_main_kernel<<<GRID, 128, sizeof(Smem)>>>(
        x, w1, b1, w2, b2, w3, b3, wp, bp, out);
}